// round 14
// baseline (speedup 1.0000x reference)
#include <cuda_runtime.h>
#include <cuda_fp16.h>
#include <cstdint>

#define NNODES 50000
#define NEDGES 800000
#define HID 64

// ---------------- scratch (static device globals; zero-initialized at load) ----------
__device__ float    g_h[NNODES * HID];
__device__ float    g_s[NNODES];
__device__ float    g_d[NNODES];
__device__ float    g_den[NNODES];      // zeroed by consumer each pass
__device__ float    g_agg[NNODES * HID];// zeroed by consumer each pass
__device__ float    g_y0[NNODES * HID];
__device__ float    g_y4[NNODES * HID];
__device__ float    g_we[4];
// B fragments (fp16 hi only), mma register order:
// layers 0-3 (NT=16): 8192 u32 each; layer 4 (NT=20): 10240 u32
__device__ uint32_t g_Bfrag[4 * 8192 + 10240];

__device__ __forceinline__ void mma_f16(float* c, const uint32_t* a, const uint32_t* b) {
    asm volatile(
        "mma.sync.aligned.m16n8k16.row.col.f32.f16.f16.f32 "
        "{%0,%1,%2,%3}, {%4,%5,%6,%7}, {%8,%9}, {%0,%1,%2,%3};"
        : "+f"(c[0]), "+f"(c[1]), "+f"(c[2]), "+f"(c[3])
        : "r"(a[0]), "r"(a[1]), "r"(a[2]), "r"(a[3]), "r"(b[0]), "r"(b[1]));
}

// ---------------- tiny prep: w = We @ ae for both GAT layers ----------------
__global__ void k_prep_we(const float* __restrict__ We1, const float* __restrict__ ae1,
                          const float* __restrict__ We2, const float* __restrict__ ae2) {
    int t = threadIdx.x;
    if (t < 4) {
        const float* W = (t < 2) ? We1 : We2;
        const float* a = (t < 2) ? ae1 : ae2;
        int r = t & 1;
        float s = 0.f;
        for (int j = 0; j < HID; j++) s += W[r * HID + j] * a[j];
        g_we[t] = s;
    }
}

// ---------------- B fragment prep: W[128,Nreal] fp32 -> fp16 (hi) mma fragments ----
__global__ void k_prep_bfrag(const float* __restrict__ W, int Nreal, int NT,
                             uint32_t* __restrict__ out) {
    int idx = blockIdx.x * blockDim.x + threadIdx.x;
    if (idx >= 8 * NT * 32) return;
    int lane = idx & 31;
    int nt = (idx >> 5) % NT;
    int kt = idx / (NT * 32);
    int g = lane >> 2, t = lane & 3;
    int n = nt * 8 + g;
    int k0 = kt * 16 + t * 2;
    float w0 = (n < Nreal) ? __ldg(W + (k0 + 0) * Nreal + n) : 0.f;
    float w1 = (n < Nreal) ? __ldg(W + (k0 + 1) * Nreal + n) : 0.f;
    float w2 = (n < Nreal) ? __ldg(W + (k0 + 8) * Nreal + n) : 0.f;
    float w3 = (n < Nreal) ? __ldg(W + (k0 + 9) * Nreal + n) : 0.f;
    __half2 h0 = __floats2half2_rn(w0, w1);
    __half2 h1 = __floats2half2_rn(w2, w3);
    uint32_t* o = out + (size_t)idx * 2;
    o[0] = *reinterpret_cast<uint32_t*>(&h0);
    o[1] = *reinterpret_cast<uint32_t*>(&h1);
}

// ---------------- node GEMM with fused normalize / zero-reset -----------------------
// MODE 0: input = X row (K=128); outputs H + scores S,D.
// MODE 2: input = relu(g_agg/g_den + bn) (K=64); writes input row to Yout;
//         zeroes g_agg row + g_den; outputs H + scores S,D.        (GAT2 front half)
// MODE 3: input = relu(g_agg/g_den + bn) + X2 row; zeroes agg/den;
//         Yout = relu(gemm + v1).                                  (l2, y1 never stored)
template <int K, int MODE>
__global__ __launch_bounds__(128) void k_node_gemm(
    const float* __restrict__ X, const float* __restrict__ X2,
    const float* __restrict__ W, const float* __restrict__ v1,
    const float* __restrict__ v2, const float* __restrict__ bn,
    float* __restrict__ Yout, float* __restrict__ H,
    float* __restrict__ S, float* __restrict__ D) {
    __shared__ float Ws[K * HID];
    __shared__ float sv1[HID], sv2[HID], sbn[HID];
    int tid = threadIdx.x;
    for (int i = tid; i < K * HID; i += 128) Ws[i] = W[i];
    if (tid < HID) {
        sv1[tid] = v1 ? v1[tid] : 0.f;
        sv2[tid] = v2 ? v2[tid] : 0.f;
        sbn[tid] = bn ? bn[tid] : 0.f;
    }
    __syncthreads();
    int node = blockIdx.x * 128 + tid;
    if (node >= NNODES) return;

    float acc[HID];
#pragma unroll
    for (int n = 0; n < HID; n++) acc[n] = 0.f;

    float rden = 0.f;
    if (MODE >= 2) {
        rden = 1.f / fmaxf(g_den[node], 1e-16f);
        g_den[node] = 0.f;
    }

    const float4* xr = (MODE == 0) ? reinterpret_cast<const float4*>(X + (size_t)node * K)
                                   : reinterpret_cast<const float4*>(&g_agg[(size_t)node * HID]);
    const float4* xr2 = (MODE == 3) ? reinterpret_cast<const float4*>(X2 + (size_t)node * K) : nullptr;
    float4* yo = (MODE == 2) ? reinterpret_cast<float4*>(Yout + (size_t)node * K) : nullptr;
    float4* az = reinterpret_cast<float4*>(&g_agg[(size_t)node * HID]);

#pragma unroll 1
    for (int k4 = 0; k4 < K / 4; k4++) {
        float4 v = __ldg(xr + k4);
        if (MODE >= 2) {
            int kb = k4 * 4;
            v.x = fmaxf(v.x * rden + sbn[kb + 0], 0.f);
            v.y = fmaxf(v.y * rden + sbn[kb + 1], 0.f);
            v.z = fmaxf(v.z * rden + sbn[kb + 2], 0.f);
            v.w = fmaxf(v.w * rden + sbn[kb + 3], 0.f);
            az[k4] = make_float4(0.f, 0.f, 0.f, 0.f);
            if (MODE == 2) yo[k4] = v;
        }
        if (MODE == 3) {
            float4 w = __ldg(xr2 + k4);
            v.x += w.x; v.y += w.y; v.z += w.z; v.w += w.w;
        }
        float xv[4] = {v.x, v.y, v.z, v.w};
#pragma unroll
        for (int kk = 0; kk < 4; kk++) {
            const float* wr = &Ws[(k4 * 4 + kk) * HID];
#pragma unroll
            for (int n = 0; n < HID; n++) acc[n] = fmaf(xv[kk], wr[n], acc[n]);
        }
    }

    if (MODE != 3) {
        float s = 0.f, d = 0.f;
#pragma unroll
        for (int n = 0; n < HID; n++) { s += acc[n] * sv1[n]; d += acc[n] * sv2[n]; }
        S[node] = s;
        D[node] = d;
        float4* hr = reinterpret_cast<float4*>(H + (size_t)node * HID);
#pragma unroll
        for (int i = 0; i < HID / 4; i++)
            hr[i] = make_float4(acc[4 * i], acc[4 * i + 1], acc[4 * i + 2], acc[4 * i + 3]);
    } else {
#pragma unroll
        for (int n = 0; n < HID; n++) acc[n] = fmaxf(acc[n] + sv1[n], 0.f);
        float4* hr = reinterpret_cast<float4*>(Yout + (size_t)node * HID);
#pragma unroll
        for (int i = 0; i < HID / 4; i++)
            hr[i] = make_float4(acc[4 * i], acc[4 * i + 1], acc[4 * i + 2], acc[4 * i + 3]);
    }
}

// ---------------- fused edge pass: logit + exp (no max; logits provably tiny) + agg -----
__global__ __launch_bounds__(256) void k_edge_agg(const int* __restrict__ EI,
                                                  const float* __restrict__ EA, int which) {
    int gid = blockIdx.x * blockDim.x + threadIdx.x;
    int e = gid >> 4;
    int q = gid & 15;
    if (e >= NEDGES) return;
    int lane = threadIdx.x & 31;
    int src = __ldg(EI + e);
    int dst = __ldg(EI + NEDGES + e);
    float ex = 0.f;
    if ((lane & 15) == 0) {
        float w0 = g_we[which * 2], w1 = g_we[which * 2 + 1];
        float lg = g_s[src] + g_d[dst] + __ldg(EA + 2 * e) * w0 + __ldg(EA + 2 * e + 1) * w1;
        lg = (lg > 0.f) ? lg : 0.2f * lg;  // leaky_relu 0.2
        ex = expf(lg);
        atomicAdd(&g_den[dst], ex);
    }
    ex = __shfl_sync(0xffffffffu, ex, lane & 16);
    float4 h4 = *reinterpret_cast<const float4*>(&g_h[(size_t)src * 64 + q * 4]);
    float vx = ex * h4.x, vy = ex * h4.y, vz = ex * h4.z, vw = ex * h4.w;
    asm volatile("red.global.add.v4.f32 [%0], {%1,%2,%3,%4};"
                 :: "l"(&g_agg[(size_t)dst * 64 + q * 4]),
                    "f"(vx), "f"(vy), "f"(vz), "f"(vw)
                 : "memory");
}

// ================= fully fused edge MLP — EXACT R10 configuration ===================
// 128-edge tile, 256 thr, occ 1 (proven optimum over R11-R13 variants).
// A kept full precision as (hi + lo) fp16; B truncated to fp16 hi (err ~2^-11).
// SMEM map (dynamic, 77696 B):
//   [0, 34816)       A hi  (128 rows x 272 B stride)
//   [34816, 69632)   A lo
//   [0, 74240)       final fp32 staging (reuses A after last mainloop)
//   [74240, 77696)   consts: We0(128f) be0(64f) b0..b3(4x128f) b4(160f)
__device__ __forceinline__ void store_hilo2(char* p, float x, float y) {
    __half2 h = __floats2half2_rn(x, y);
    float2 f = __half22float2(h);
    __half2 l = __floats2half2_rn(x - f.x, y - f.y);
    *reinterpret_cast<uint32_t*>(p) = *reinterpret_cast<uint32_t*>(&h);
    *reinterpret_cast<uint32_t*>(p + 34816) = *reinterpret_cast<uint32_t*>(&l);
}

template <int NTW>
__device__ __forceinline__ void mlp_mainloop(
    const char* sm, const uint32_t* __restrict__ Bf,
    int wm, int wn, int lane, float (&acc)[4][NTW][4]) {
    constexpr int NT = 4 * NTW;
    const int g = lane >> 2, t = lane & 3;
#pragma unroll
    for (int a = 0; a < 4; a++)
#pragma unroll
        for (int b = 0; b < NTW; b++)
#pragma unroll
            for (int c = 0; c < 4; c++) acc[a][b][c] = 0.f;
#pragma unroll 1
    for (int kt = 0; kt < 8; kt++) {
        uint32_t bh[NTW][2];
        const uint32_t* bp = Bf + ((size_t)(kt * NT + wn * NTW) * 32 + lane) * 2;
#pragma unroll
        for (int nt = 0; nt < NTW; nt++) {
            bh[nt][0] = __ldg(bp + nt * 64 + 0);
            bh[nt][1] = __ldg(bp + nt * 64 + 1);
        }
#pragma unroll
        for (int mt = 0; mt < 4; mt++) {
            const char* Ah = sm + (wm * 64 + mt * 16 + g) * 272 + (kt * 16 + t * 2) * 2;
            uint32_t ah[4], al[4];
            ah[0] = *reinterpret_cast<const uint32_t*>(Ah);
            ah[1] = *reinterpret_cast<const uint32_t*>(Ah + 8 * 272);
            ah[2] = *reinterpret_cast<const uint32_t*>(Ah + 16);
            ah[3] = *reinterpret_cast<const uint32_t*>(Ah + 8 * 272 + 16);
            al[0] = *reinterpret_cast<const uint32_t*>(Ah + 34816);
            al[1] = *reinterpret_cast<const uint32_t*>(Ah + 34816 + 8 * 272);
            al[2] = *reinterpret_cast<const uint32_t*>(Ah + 34816 + 16);
            al[3] = *reinterpret_cast<const uint32_t*>(Ah + 34816 + 8 * 272 + 16);
#pragma unroll
            for (int nt = 0; nt < NTW; nt++) {
                mma_f16(acc[mt][nt], ah, bh[nt]);
                mma_f16(acc[mt][nt], al, bh[nt]);
            }
        }
    }
}

__global__ __launch_bounds__(256) void k_mlp(
    const int* __restrict__ EI, const float* __restrict__ EA,
    const float* __restrict__ Y4, const uint32_t* __restrict__ Bf,
    const float* __restrict__ We0, const float* __restrict__ be0,
    const float* __restrict__ b3, const float* __restrict__ bm0,
    const float* __restrict__ bm1, const float* __restrict__ bm2,
    const float* __restrict__ b4, float* __restrict__ out) {
    extern __shared__ char sm[];
    float* cs = reinterpret_cast<float*>(sm + 74240);
    const int tid = threadIdx.x;
    const int wid = tid >> 5, lane = tid & 31;
    const int g = lane >> 2, t = lane & 3;
    const int wm = wid >> 2, wn = wid & 3;
    const int m0 = blockIdx.x * 128;

    // consts -> smem
    for (int i = tid; i < 128; i += 256) {
        cs[i] = __ldg(We0 + i);
        cs[192 + i] = __ldg(b3 + i);
        cs[320 + i] = __ldg(bm0 + i);
        cs[448 + i] = __ldg(bm1 + i);
        cs[576 + i] = __ldg(bm2 + i);
    }
    for (int i = tid; i < 64; i += 256) cs[128 + i] = __ldg(be0 + i);
    for (int i = tid; i < 160; i += 256) cs[704 + i] = (i < 145) ? __ldg(b4 + i) : 0.f;
    __syncthreads();

    // stage layer-0 input: [y4[src]+y4[dst] | relu(ea@We0+be0)] -> hi/lo fp16 SMEM
#pragma unroll
    for (int it = 0; it < 16; it++) {
        int i = tid + it * 256;
        int row = i >> 5, col = (i & 31) * 4;
        int e = m0 + row;
        float4 v;
        if (col < 64) {
            int s = __ldg(EI + e), d = __ldg(EI + NEDGES + e);
            float4 a = *reinterpret_cast<const float4*>(Y4 + (size_t)s * 64 + col);
            float4 b = *reinterpret_cast<const float4*>(Y4 + (size_t)d * 64 + col);
            v = make_float4(a.x + b.x, a.y + b.y, a.z + b.z, a.w + b.w);
        } else {
            int c2 = col - 64;
            float e0 = __ldg(EA + 2 * e), e1 = __ldg(EA + 2 * e + 1);
            v.x = fmaxf(e0 * cs[c2 + 0] + e1 * cs[64 + c2 + 0] + cs[128 + c2 + 0], 0.f);
            v.y = fmaxf(e0 * cs[c2 + 1] + e1 * cs[64 + c2 + 1] + cs[128 + c2 + 1], 0.f);
            v.z = fmaxf(e0 * cs[c2 + 2] + e1 * cs[64 + c2 + 2] + cs[128 + c2 + 2], 0.f);
            v.w = fmaxf(e0 * cs[c2 + 3] + e1 * cs[64 + c2 + 3] + cs[128 + c2 + 3], 0.f);
        }
        char* p = sm + row * 272 + col * 2;
        store_hilo2(p, v.x, v.y);
        store_hilo2(p + 4, v.z, v.w);
    }
    __syncthreads();

    // 4 hidden layers, resident in SMEM
#pragma unroll 1
    for (int l = 0; l < 4; l++) {
        float acc[4][4][4];
        mlp_mainloop<4>(sm, Bf + l * 8192, wm, wn, lane, acc);
        __syncthreads();  // all A reads done before overwrite
        const float* bs = cs + 192 + l * 128;
#pragma unroll
        for (int mt = 0; mt < 4; mt++) {
            int r0 = wm * 64 + mt * 16 + g;
#pragma unroll
            for (int nt = 0; nt < 4; nt++) {
                int c0 = wn * 32 + nt * 8 + t * 2;
                float bv0 = bs[c0], bv1 = bs[c0 + 1];
                char* p0 = sm + r0 * 272 + c0 * 2;
                store_hilo2(p0, fmaxf(acc[mt][nt][0] + bv0, 0.f),
                                fmaxf(acc[mt][nt][1] + bv1, 0.f));
                store_hilo2(p0 + 8 * 272, fmaxf(acc[mt][nt][2] + bv0, 0.f),
                                          fmaxf(acc[mt][nt][3] + bv1, 0.f));
            }
        }
        __syncthreads();
    }

    // final layer: 160 padded cols, 145 real
    {
        float acc[4][5][4];
        mlp_mainloop<5>(sm, Bf + 4 * 8192, wm, wn, lane, acc);
        __syncthreads();
        float* epi = reinterpret_cast<float*>(sm);
        const float* bs = cs + 704;
#pragma unroll
        for (int mt = 0; mt < 4; mt++) {
            int r0 = wm * 64 + mt * 16 + g;
#pragma unroll
            for (int nt = 0; nt < 5; nt++) {
                int c0 = wn * 40 + nt * 8 + t * 2;
                float bv0 = bs[c0], bv1 = bs[c0 + 1];
                if (c0 < 145) {
                    epi[r0 * 145 + c0] = acc[mt][nt][0] + bv0;
                    epi[(r0 + 8) * 145 + c0] = acc[mt][nt][2] + bv0;
                }
                if (c0 + 1 < 145) {
                    epi[r0 * 145 + c0 + 1] = acc[mt][nt][1] + bv1;
                    epi[(r0 + 8) * 145 + c0 + 1] = acc[mt][nt][3] + bv1;
                }
            }
        }
        __syncthreads();
        float* Co = out + (size_t)m0 * 145;
        for (int i = tid; i < 128 * 145; i += 256) Co[i] = epi[i];
    }
}

// ---------------- launch ----------------
extern "C" void kernel_launch(void* const* d_in, const int* in_sizes, int n_in,
                              void* d_out, int out_size) {
    const float* x   = (const float*)d_in[0];
    const int*   ei  = (const int*)d_in[1];
    const float* ea  = (const float*)d_in[2];
    const float* Wg1 = (const float*)d_in[4];
    const float* as1 = (const float*)d_in[5];
    const float* ad1 = (const float*)d_in[6];
    const float* We1 = (const float*)d_in[7];
    const float* ae1 = (const float*)d_in[8];
    const float* bg1 = (const float*)d_in[9];
    const float* Wg2 = (const float*)d_in[10];
    const float* as2 = (const float*)d_in[11];
    const float* ad2 = (const float*)d_in[12];
    const float* We2 = (const float*)d_in[13];
    const float* ae2 = (const float*)d_in[14];
    const float* bg2 = (const float*)d_in[15];
    const float* W2  = (const float*)d_in[16];
    const float* b2  = (const float*)d_in[17];
    const float* We0 = (const float*)d_in[18];
    const float* be0 = (const float*)d_in[19];
    const float* W3  = (const float*)d_in[20];
    const float* b3  = (const float*)d_in[21];
    const float* Wm0 = (const float*)d_in[22];
    const float* bm0 = (const float*)d_in[23];
    const float* Wm1 = (const float*)d_in[24];
    const float* bm1 = (const float*)d_in[25];
    const float* Wm2 = (const float*)d_in[26];
    const float* bm2 = (const float*)d_in[27];
    const float* W4  = (const float*)d_in[28];
    const float* b4  = (const float*)d_in[29];
    float* out = (float*)d_out;

    float *p_h, *p_s, *p_d, *p_y0, *p_y4;
    uint32_t* p_BF;
    cudaGetSymbolAddress((void**)&p_h, g_h);
    cudaGetSymbolAddress((void**)&p_s, g_s);
    cudaGetSymbolAddress((void**)&p_d, g_d);
    cudaGetSymbolAddress((void**)&p_y0, g_y0);
    cudaGetSymbolAddress((void**)&p_y4, g_y4);
    cudaGetSymbolAddress((void**)&p_BF, g_Bfrag);

    const int SMM = 77696;  // dynamic smem for k_mlp
    cudaFuncSetAttribute(k_mlp, cudaFuncAttributeMaxDynamicSharedMemorySize, SMM);

    const int nodeGrid = (NNODES + 127) / 128;
    const int aggGrid  = (NEDGES * 16) / 256;  // 50000

    k_prep_we<<<1, 32>>>(We1, ae1, We2, ae2);

    // B fragments for the 5 tensor GEMMs (fp16 hi only)
    k_prep_bfrag<<<(8 * 16 * 32 + 255) / 256, 256>>>(W3,  128, 16, p_BF + 0 * 8192);
    k_prep_bfrag<<<(8 * 16 * 32 + 255) / 256, 256>>>(Wm0, 128, 16, p_BF + 1 * 8192);
    k_prep_bfrag<<<(8 * 16 * 32 + 255) / 256, 256>>>(Wm1, 128, 16, p_BF + 2 * 8192);
    k_prep_bfrag<<<(8 * 16 * 32 + 255) / 256, 256>>>(Wm2, 128, 16, p_BF + 3 * 8192);
    k_prep_bfrag<<<(8 * 20 * 32 + 255) / 256, 256>>>(W4,  145, 20, p_BF + 4 * 8192);

    // ---- GAT layer 1 (agg/den zero: zero-init at load, re-zeroed per pass by consumers) ----
    k_node_gemm<128, 0><<<nodeGrid, 128>>>(x, nullptr, Wg1, as1, ad1, nullptr,
                                           nullptr, p_h, p_s, p_d);
    k_edge_agg<<<aggGrid, 256>>>(ei, ea, 0);

    // ---- GAT layer 2 front half: y0 = relu(agg/den + bg1) fused; zero agg/den ----
    k_node_gemm<64, 2><<<nodeGrid, 128>>>(nullptr, nullptr, Wg2, as2, ad2, bg1,
                                          p_y0, p_h, p_s, p_d);
    k_edge_agg<<<aggGrid, 256>>>(ei, ea, 1);

    // ---- l2 fused: y1 = relu(agg/den + bg2) inline; y4 = relu((y0+y1)@W2 + b2) ----
    k_node_gemm<64, 3><<<nodeGrid, 128>>>(nullptr, p_y0, W2, b2, nullptr, bg2,
                                          p_y4, nullptr, nullptr, nullptr);

    // ---- fully fused edge MLP (EXACT R10 config, occ 1) ----
    k_mlp<<<NEDGES / 128, 256, SMM>>>(ei, ea, p_y4, p_BF, We0, be0, b3, bm0, bm1, bm2, b4, out);
}

// round 15
// speedup vs baseline: 1.3071x; 1.3071x over previous
#include <cuda_runtime.h>
#include <cuda_fp16.h>
#include <cstdint>

#define NNODES 50000
#define NEDGES 800000
#define HID 64

// ---------------- scratch (static device globals; no allocation) ----------------
__device__ float    g_h[NNODES * HID];
__device__ float    g_s[NNODES];
__device__ float    g_d[NNODES];
__device__ float    g_den[NNODES];
__device__ float    g_agg[NNODES * HID];
__device__ float    g_y0[NNODES * HID];
__device__ float    g_y1[NNODES * HID];
__device__ float    g_y4[NNODES * HID];
__device__ float    g_we[4];
// B fragments (fp16 hi only), mma register order:
// layers 0-3 (NT=16): 8192 u32 each; layer 4 (NT=20): 10240 u32
__device__ uint32_t g_Bfrag[4 * 8192 + 10240];

__device__ __forceinline__ void mma_f16(float* c, const uint32_t* a, const uint32_t* b) {
    asm volatile(
        "mma.sync.aligned.m16n8k16.row.col.f32.f16.f16.f32 "
        "{%0,%1,%2,%3}, {%4,%5,%6,%7}, {%8,%9}, {%0,%1,%2,%3};"
        : "+f"(c[0]), "+f"(c[1]), "+f"(c[2]), "+f"(c[3])
        : "r"(a[0]), "r"(a[1]), "r"(a[2]), "r"(a[3]), "r"(b[0]), "r"(b[1]));
}

// ---------------- tiny prep: w = We @ ae for both GAT layers ----------------
__global__ void k_prep_we(const float* __restrict__ We1, const float* __restrict__ ae1,
                          const float* __restrict__ We2, const float* __restrict__ ae2) {
    int t = threadIdx.x;
    if (t < 4) {
        const float* W = (t < 2) ? We1 : We2;
        const float* a = (t < 2) ? ae1 : ae2;
        int r = t & 1;
        float s = 0.f;
        for (int j = 0; j < HID; j++) s += W[r * HID + j] * a[j];
        g_we[t] = s;
    }
}

// ---------------- B fragment prep: W[128,Nreal] fp32 -> fp16 (hi) mma fragments ----
__global__ void k_prep_bfrag(const float* __restrict__ W, int Nreal, int NT,
                             uint32_t* __restrict__ out) {
    int idx = blockIdx.x * blockDim.x + threadIdx.x;
    if (idx >= 8 * NT * 32) return;
    int lane = idx & 31;
    int nt = (idx >> 5) % NT;
    int kt = idx / (NT * 32);
    int g = lane >> 2, t = lane & 3;
    int n = nt * 8 + g;
    int k0 = kt * 16 + t * 2;
    float w0 = (n < Nreal) ? __ldg(W + (k0 + 0) * Nreal + n) : 0.f;
    float w1 = (n < Nreal) ? __ldg(W + (k0 + 1) * Nreal + n) : 0.f;
    float w2 = (n < Nreal) ? __ldg(W + (k0 + 8) * Nreal + n) : 0.f;
    float w3 = (n < Nreal) ? __ldg(W + (k0 + 9) * Nreal + n) : 0.f;
    __half2 h0 = __floats2half2_rn(w0, w1);
    __half2 h1 = __floats2half2_rn(w2, w3);
    uint32_t* o = out + (size_t)idx * 2;
    o[0] = *reinterpret_cast<uint32_t*>(&h0);
    o[1] = *reinterpret_cast<uint32_t*>(&h1);
}

// ---------------- per-call re-init of aggregation scratch ----------------
__global__ void k_init() {
    int gid = blockIdx.x * blockDim.x + threadIdx.x;
    if (gid < NNODES * HID) g_agg[gid] = 0.f;
    if (gid < NNODES) g_den[gid] = 0.f;
}

// ---------------- node GEMM (small, stays fp32 scalar) ----------------
template <int K, int MODE>
__global__ __launch_bounds__(128) void k_node_gemm(
    const float* __restrict__ X, const float* __restrict__ X2,
    const float* __restrict__ W, const float* __restrict__ v1,
    const float* __restrict__ v2,
    float* __restrict__ H, float* __restrict__ S, float* __restrict__ D) {
    __shared__ float Ws[K * HID];
    __shared__ float sv1[HID], sv2[HID];
    int tid = threadIdx.x;
    for (int i = tid; i < K * HID; i += 128) Ws[i] = W[i];
    if (tid < HID) {
        sv1[tid] = v1 ? v1[tid] : 0.f;
        sv2[tid] = v2 ? v2[tid] : 0.f;
    }
    __syncthreads();
    int node = blockIdx.x * 128 + tid;
    if (node >= NNODES) return;

    float acc[HID];
#pragma unroll
    for (int n = 0; n < HID; n++) acc[n] = 0.f;

    const float4* xr = reinterpret_cast<const float4*>(X + (size_t)node * K);
    const float4* xr2 = (MODE == 1) ? reinterpret_cast<const float4*>(X2 + (size_t)node * K) : nullptr;
#pragma unroll 1
    for (int k4 = 0; k4 < K / 4; k4++) {
        float4 v = __ldg(xr + k4);
        if (MODE == 1) {
            float4 w = __ldg(xr2 + k4);
            v.x += w.x; v.y += w.y; v.z += w.z; v.w += w.w;
        }
        float xv[4] = {v.x, v.y, v.z, v.w};
#pragma unroll
        for (int kk = 0; kk < 4; kk++) {
            const float* wr = &Ws[(k4 * 4 + kk) * HID];
#pragma unroll
            for (int n = 0; n < HID; n++) acc[n] = fmaf(xv[kk], wr[n], acc[n]);
        }
    }

    if (MODE == 0) {
        float s = 0.f, d = 0.f;
#pragma unroll
        for (int n = 0; n < HID; n++) { s += acc[n] * sv1[n]; d += acc[n] * sv2[n]; }
        S[node] = s;
        D[node] = d;
    } else {
#pragma unroll
        for (int n = 0; n < HID; n++) acc[n] = fmaxf(acc[n] + sv1[n], 0.f);
    }
    float4* hr = reinterpret_cast<float4*>(H + (size_t)node * HID);
#pragma unroll
    for (int i = 0; i < HID / 4; i++)
        hr[i] = make_float4(acc[4 * i], acc[4 * i + 1], acc[4 * i + 2], acc[4 * i + 3]);
}

// ---------------- fused edge pass: logit + exp (no max; logits provably tiny) + agg -----
__global__ __launch_bounds__(256) void k_edge_agg(const int* __restrict__ EI,
                                                  const float* __restrict__ EA, int which) {
    int gid = blockIdx.x * blockDim.x + threadIdx.x;
    int e = gid >> 4;
    int q = gid & 15;
    if (e >= NEDGES) return;
    int lane = threadIdx.x & 31;
    int src = __ldg(EI + e);
    int dst = __ldg(EI + NEDGES + e);
    float ex = 0.f;
    if ((lane & 15) == 0) {
        float w0 = g_we[which * 2], w1 = g_we[which * 2 + 1];
        float lg = g_s[src] + g_d[dst] + __ldg(EA + 2 * e) * w0 + __ldg(EA + 2 * e + 1) * w1;
        lg = (lg > 0.f) ? lg : 0.2f * lg;  // leaky_relu 0.2
        ex = expf(lg);
        atomicAdd(&g_den[dst], ex);
    }
    ex = __shfl_sync(0xffffffffu, ex, lane & 16);
    float4 h4 = *reinterpret_cast<const float4*>(&g_h[(size_t)src * 64 + q * 4]);
    float vx = ex * h4.x, vy = ex * h4.y, vz = ex * h4.z, vw = ex * h4.w;
    asm volatile("red.global.add.v4.f32 [%0], {%1,%2,%3,%4};"
                 :: "l"(&g_agg[(size_t)dst * 64 + q * 4]),
                    "f"(vx), "f"(vy), "f"(vz), "f"(vw)
                 : "memory");
}

// ---------------- normalize + bias + relu ----------------
__global__ void k_node_fin(const float* __restrict__ bias, float* __restrict__ Y) {
    int gid = blockIdx.x * blockDim.x + threadIdx.x;
    if (gid >= NNODES * HID) return;
    int n = gid & 63;
    float den = fmaxf(g_den[gid >> 6], 1e-16f);
    Y[gid] = fmaxf(g_agg[gid] / den + __ldg(bias + n), 0.f);
}

// ================= fully fused edge MLP (gather + 5 pure-fp16 HMMA layers) =========
// R10 structure, but 1-term fp16 (A hi only): half the HMMA count of R10.
// Calibrated error model: bf16 3-term 1.7e-6, fp16 2-term 7.6e-5 -> 1-term ~1.5e-4.
// SMEM map (dynamic, 77696 B):
//   [0, 34816)       A hi  (128 rows x 272 B stride)
//   [0, 74240)       final fp32 staging (reuses A after last mainloop)
//   [74240, 77696)   consts: We0(128f) be0(64f) b0..b3(4x128f) b4(160f)
__device__ __forceinline__ void store_hi2(char* p, float x, float y) {
    __half2 h = __floats2half2_rn(x, y);
    *reinterpret_cast<uint32_t*>(p) = *reinterpret_cast<uint32_t*>(&h);
}

template <int NTW>
__device__ __forceinline__ void mlp_mainloop(
    const char* sm, const uint32_t* __restrict__ Bf,
    int wm, int wn, int lane, float (&acc)[4][NTW][4]) {
    constexpr int NT = 4 * NTW;
    const int g = lane >> 2, t = lane & 3;
#pragma unroll
    for (int a = 0; a < 4; a++)
#pragma unroll
        for (int b = 0; b < NTW; b++)
#pragma unroll
            for (int c = 0; c < 4; c++) acc[a][b][c] = 0.f;
#pragma unroll 1
    for (int kt = 0; kt < 8; kt++) {
        uint32_t bh[NTW][2];
        const uint32_t* bp = Bf + ((size_t)(kt * NT + wn * NTW) * 32 + lane) * 2;
#pragma unroll
        for (int nt = 0; nt < NTW; nt++) {
            bh[nt][0] = __ldg(bp + nt * 64 + 0);
            bh[nt][1] = __ldg(bp + nt * 64 + 1);
        }
#pragma unroll
        for (int mt = 0; mt < 4; mt++) {
            const char* Ah = sm + (wm * 64 + mt * 16 + g) * 272 + (kt * 16 + t * 2) * 2;
            uint32_t ah[4];
            ah[0] = *reinterpret_cast<const uint32_t*>(Ah);
            ah[1] = *reinterpret_cast<const uint32_t*>(Ah + 8 * 272);
            ah[2] = *reinterpret_cast<const uint32_t*>(Ah + 16);
            ah[3] = *reinterpret_cast<const uint32_t*>(Ah + 8 * 272 + 16);
#pragma unroll
            for (int nt = 0; nt < NTW; nt++) {
                mma_f16(acc[mt][nt], ah, bh[nt]);
            }
        }
    }
}

__global__ __launch_bounds__(256) void k_mlp(
    const int* __restrict__ EI, const float* __restrict__ EA,
    const float* __restrict__ Y4, const uint32_t* __restrict__ Bf,
    const float* __restrict__ We0, const float* __restrict__ be0,
    const float* __restrict__ b3, const float* __restrict__ bm0,
    const float* __restrict__ bm1, const float* __restrict__ bm2,
    const float* __restrict__ b4, float* __restrict__ out) {
    extern __shared__ char sm[];
    float* cs = reinterpret_cast<float*>(sm + 74240);
    const int tid = threadIdx.x;
    const int wid = tid >> 5, lane = tid & 31;
    const int g = lane >> 2, t = lane & 3;
    const int wm = wid >> 2, wn = wid & 3;
    const int m0 = blockIdx.x * 128;

    // consts -> smem
    for (int i = tid; i < 128; i += 256) {
        cs[i] = __ldg(We0 + i);
        cs[192 + i] = __ldg(b3 + i);
        cs[320 + i] = __ldg(bm0 + i);
        cs[448 + i] = __ldg(bm1 + i);
        cs[576 + i] = __ldg(bm2 + i);
    }
    for (int i = tid; i < 64; i += 256) cs[128 + i] = __ldg(be0 + i);
    for (int i = tid; i < 160; i += 256) cs[704 + i] = (i < 145) ? __ldg(b4 + i) : 0.f;
    __syncthreads();

    // stage layer-0 input: [y4[src]+y4[dst] | relu(ea@We0+be0)] -> fp16 SMEM
#pragma unroll
    for (int it = 0; it < 16; it++) {
        int i = tid + it * 256;
        int row = i >> 5, col = (i & 31) * 4;
        int e = m0 + row;
        float4 v;
        if (col < 64) {
            int s = __ldg(EI + e), d = __ldg(EI + NEDGES + e);
            float4 a = *reinterpret_cast<const float4*>(Y4 + (size_t)s * 64 + col);
            float4 b = *reinterpret_cast<const float4*>(Y4 + (size_t)d * 64 + col);
            v = make_float4(a.x + b.x, a.y + b.y, a.z + b.z, a.w + b.w);
        } else {
            int c2 = col - 64;
            float e0 = __ldg(EA + 2 * e), e1 = __ldg(EA + 2 * e + 1);
            v.x = fmaxf(e0 * cs[c2 + 0] + e1 * cs[64 + c2 + 0] + cs[128 + c2 + 0], 0.f);
            v.y = fmaxf(e0 * cs[c2 + 1] + e1 * cs[64 + c2 + 1] + cs[128 + c2 + 1], 0.f);
            v.z = fmaxf(e0 * cs[c2 + 2] + e1 * cs[64 + c2 + 2] + cs[128 + c2 + 2], 0.f);
            v.w = fmaxf(e0 * cs[c2 + 3] + e1 * cs[64 + c2 + 3] + cs[128 + c2 + 3], 0.f);
        }
        char* p = sm + row * 272 + col * 2;
        store_hi2(p, v.x, v.y);
        store_hi2(p + 4, v.z, v.w);
    }
    __syncthreads();

    // 4 hidden layers, resident in SMEM
#pragma unroll 1
    for (int l = 0; l < 4; l++) {
        float acc[4][4][4];
        mlp_mainloop<4>(sm, Bf + l * 8192, wm, wn, lane, acc);
        __syncthreads();  // all A reads done before overwrite
        const float* bs = cs + 192 + l * 128;
#pragma unroll
        for (int mt = 0; mt < 4; mt++) {
            int r0 = wm * 64 + mt * 16 + g;
#pragma unroll
            for (int nt = 0; nt < 4; nt++) {
                int c0 = wn * 32 + nt * 8 + t * 2;
                float bv0 = bs[c0], bv1 = bs[c0 + 1];
                char* p0 = sm + r0 * 272 + c0 * 2;
                store_hi2(p0, fmaxf(acc[mt][nt][0] + bv0, 0.f),
                              fmaxf(acc[mt][nt][1] + bv1, 0.f));
                store_hi2(p0 + 8 * 272, fmaxf(acc[mt][nt][2] + bv0, 0.f),
                                        fmaxf(acc[mt][nt][3] + bv1, 0.f));
            }
        }
        __syncthreads();
    }

    // final layer: 160 padded cols, 145 real
    {
        float acc[4][5][4];
        mlp_mainloop<5>(sm, Bf + 4 * 8192, wm, wn, lane, acc);
        __syncthreads();
        float* epi = reinterpret_cast<float*>(sm);
        const float* bs = cs + 704;
#pragma unroll
        for (int mt = 0; mt < 4; mt++) {
            int r0 = wm * 64 + mt * 16 + g;
#pragma unroll
            for (int nt = 0; nt < 5; nt++) {
                int c0 = wn * 40 + nt * 8 + t * 2;
                float bv0 = bs[c0], bv1 = bs[c0 + 1];
                if (c0 < 145) {
                    epi[r0 * 145 + c0] = acc[mt][nt][0] + bv0;
                    epi[(r0 + 8) * 145 + c0] = acc[mt][nt][2] + bv0;
                }
                if (c0 + 1 < 145) {
                    epi[r0 * 145 + c0 + 1] = acc[mt][nt][1] + bv1;
                    epi[(r0 + 8) * 145 + c0 + 1] = acc[mt][nt][3] + bv1;
                }
            }
        }
        __syncthreads();
        float* Co = out + (size_t)m0 * 145;
        for (int i = tid; i < 128 * 145; i += 256) Co[i] = epi[i];
    }
}

// ---------------- launch ----------------
extern "C" void kernel_launch(void* const* d_in, const int* in_sizes, int n_in,
                              void* d_out, int out_size) {
    const float* x   = (const float*)d_in[0];
    const int*   ei  = (const int*)d_in[1];
    const float* ea  = (const float*)d_in[2];
    const float* Wg1 = (const float*)d_in[4];
    const float* as1 = (const float*)d_in[5];
    const float* ad1 = (const float*)d_in[6];
    const float* We1 = (const float*)d_in[7];
    const float* ae1 = (const float*)d_in[8];
    const float* bg1 = (const float*)d_in[9];
    const float* Wg2 = (const float*)d_in[10];
    const float* as2 = (const float*)d_in[11];
    const float* ad2 = (const float*)d_in[12];
    const float* We2 = (const float*)d_in[13];
    const float* ae2 = (const float*)d_in[14];
    const float* bg2 = (const float*)d_in[15];
    const float* W2  = (const float*)d_in[16];
    const float* b2  = (const float*)d_in[17];
    const float* We0 = (const float*)d_in[18];
    const float* be0 = (const float*)d_in[19];
    const float* W3  = (const float*)d_in[20];
    const float* b3  = (const float*)d_in[21];
    const float* Wm0 = (const float*)d_in[22];
    const float* bm0 = (const float*)d_in[23];
    const float* Wm1 = (const float*)d_in[24];
    const float* bm1 = (const float*)d_in[25];
    const float* Wm2 = (const float*)d_in[26];
    const float* bm2 = (const float*)d_in[27];
    const float* W4  = (const float*)d_in[28];
    const float* b4  = (const float*)d_in[29];
    float* out = (float*)d_out;

    float *p_h, *p_s, *p_d, *p_y0, *p_y1, *p_y4;
    uint32_t* p_BF;
    cudaGetSymbolAddress((void**)&p_h, g_h);
    cudaGetSymbolAddress((void**)&p_s, g_s);
    cudaGetSymbolAddress((void**)&p_d, g_d);
    cudaGetSymbolAddress((void**)&p_y0, g_y0);
    cudaGetSymbolAddress((void**)&p_y1, g_y1);
    cudaGetSymbolAddress((void**)&p_y4, g_y4);
    cudaGetSymbolAddress((void**)&p_BF, g_Bfrag);

    const int SMM = 77696;  // dynamic smem for k_mlp
    cudaFuncSetAttribute(k_mlp, cudaFuncAttributeMaxDynamicSharedMemorySize, SMM);

    const int initGrid = (NNODES * HID + 255) / 256;
    const int nodeGrid = (NNODES + 127) / 128;
    const int aggGrid  = (NEDGES * 16) / 256;  // 50000

    k_prep_we<<<1, 32>>>(We1, ae1, We2, ae2);

    // B fragments for the 5 tensor GEMMs (fp16 hi only)
    k_prep_bfrag<<<(8 * 16 * 32 + 255) / 256, 256>>>(W3,  128, 16, p_BF + 0 * 8192);
    k_prep_bfrag<<<(8 * 16 * 32 + 255) / 256, 256>>>(Wm0, 128, 16, p_BF + 1 * 8192);
    k_prep_bfrag<<<(8 * 16 * 32 + 255) / 256, 256>>>(Wm1, 128, 16, p_BF + 2 * 8192);
    k_prep_bfrag<<<(8 * 16 * 32 + 255) / 256, 256>>>(Wm2, 128, 16, p_BF + 3 * 8192);
    k_prep_bfrag<<<(8 * 20 * 32 + 255) / 256, 256>>>(W4,  145, 20, p_BF + 4 * 8192);

    // ---- GAT layer 1 ----
    k_init<<<initGrid, 256>>>();
    k_node_gemm<128, 0><<<nodeGrid, 128>>>(x, nullptr, Wg1, as1, ad1, p_h, p_s, p_d);
    k_edge_agg<<<aggGrid, 256>>>(ei, ea, 0);
    k_node_fin<<<initGrid, 256>>>(bg1, p_y0);

    // ---- GAT layer 2 ----
    k_init<<<initGrid, 256>>>();
    k_node_gemm<64, 0><<<nodeGrid, 128>>>(p_y0, nullptr, Wg2, as2, ad2, p_h, p_s, p_d);
    k_edge_agg<<<aggGrid, 256>>>(ei, ea, 1);
    k_node_fin<<<initGrid, 256>>>(bg2, p_y1);

    // ---- l2: y4 = relu((y0+y1) @ W2 + b2) ----
    k_node_gemm<64, 1><<<nodeGrid, 128>>>(p_y0, p_y1, W2, b2, nullptr, p_y4, nullptr, nullptr);

    // ---- fully fused edge MLP (pure fp16, 1 mma/tile) ----
    k_mlp<<<NEDGES / 128, 256, SMM>>>(ei, ea, p_y4, p_BF, We0, be0, b3, bm0, bm1, bm2, b4, out);
}

// round 16
// speedup vs baseline: 1.3866x; 1.0608x over previous
#include <cuda_runtime.h>
#include <cuda_fp16.h>
#include <cstdint>

#define NNODES 50000
#define NEDGES 800000
#define HID 64

// ---------------- scratch (static device globals; zero-initialized at load) ----------
// g_agg re-zeroed by k_node_fin after consumption; g_den re-zeroed by the node GEMM
// that follows each fin (and by l2 gemm for next replay) -> state restored every call.
__device__ float    g_h[NNODES * HID];
__device__ float    g_s[NNODES];
__device__ float    g_d[NNODES];
__device__ float    g_den[NNODES];
__device__ float    g_agg[NNODES * HID];
__device__ float    g_y0[NNODES * HID];
__device__ float    g_y1[NNODES * HID];
__device__ float    g_y4[NNODES * HID];
__device__ float    g_we[4];
// B fragments (fp16 hi only), mma register order:
// layers 0-3 (NT=16): 8192 u32 each; layer 4 (NT=20): 10240 u32
__device__ uint32_t g_Bfrag[4 * 8192 + 10240];

__device__ __forceinline__ void mma_f16(float* c, const uint32_t* a, const uint32_t* b) {
    asm volatile(
        "mma.sync.aligned.m16n8k16.row.col.f32.f16.f16.f32 "
        "{%0,%1,%2,%3}, {%4,%5,%6,%7}, {%8,%9}, {%0,%1,%2,%3};"
        : "+f"(c[0]), "+f"(c[1]), "+f"(c[2]), "+f"(c[3])
        : "r"(a[0]), "r"(a[1]), "r"(a[2]), "r"(a[3]), "r"(b[0]), "r"(b[1]));
}

// ---------------- tiny prep: w = We @ ae for both GAT layers ----------------
__global__ void k_prep_we(const float* __restrict__ We1, const float* __restrict__ ae1,
                          const float* __restrict__ We2, const float* __restrict__ ae2) {
    int t = threadIdx.x;
    if (t < 4) {
        const float* W = (t < 2) ? We1 : We2;
        const float* a = (t < 2) ? ae1 : ae2;
        int r = t & 1;
        float s = 0.f;
        for (int j = 0; j < HID; j++) s += W[r * HID + j] * a[j];
        g_we[t] = s;
    }
}

// ---------------- B fragment prep: W[128,Nreal] fp32 -> fp16 (hi) mma fragments ----
__global__ void k_prep_bfrag(const float* __restrict__ W, int Nreal, int NT,
                             uint32_t* __restrict__ out) {
    int idx = blockIdx.x * blockDim.x + threadIdx.x;
    if (idx >= 8 * NT * 32) return;
    int lane = idx & 31;
    int nt = (idx >> 5) % NT;
    int kt = idx / (NT * 32);
    int g = lane >> 2, t = lane & 3;
    int n = nt * 8 + g;
    int k0 = kt * 16 + t * 2;
    float w0 = (n < Nreal) ? __ldg(W + (k0 + 0) * Nreal + n) : 0.f;
    float w1 = (n < Nreal) ? __ldg(W + (k0 + 1) * Nreal + n) : 0.f;
    float w2 = (n < Nreal) ? __ldg(W + (k0 + 8) * Nreal + n) : 0.f;
    float w3 = (n < Nreal) ? __ldg(W + (k0 + 9) * Nreal + n) : 0.f;
    __half2 h0 = __floats2half2_rn(w0, w1);
    __half2 h1 = __floats2half2_rn(w2, w3);
    uint32_t* o = out + (size_t)idx * 2;
    o[0] = *reinterpret_cast<uint32_t*>(&h0);
    o[1] = *reinterpret_cast<uint32_t*>(&h1);
}

// ---------------- node GEMM (fp32 scalar); ZD: zero g_den[node] for next pass -------
template <int K, int MODE, bool ZD>
__global__ __launch_bounds__(128) void k_node_gemm(
    const float* __restrict__ X, const float* __restrict__ X2,
    const float* __restrict__ W, const float* __restrict__ v1,
    const float* __restrict__ v2,
    float* __restrict__ H, float* __restrict__ S, float* __restrict__ D) {
    __shared__ float Ws[K * HID];
    __shared__ float sv1[HID], sv2[HID];
    int tid = threadIdx.x;
    for (int i = tid; i < K * HID; i += 128) Ws[i] = W[i];
    if (tid < HID) {
        sv1[tid] = v1 ? v1[tid] : 0.f;
        sv2[tid] = v2 ? v2[tid] : 0.f;
    }
    __syncthreads();
    int node = blockIdx.x * 128 + tid;
    if (node >= NNODES) return;

    if (ZD) g_den[node] = 0.f;  // reset for the next edge-agg pass / next replay

    float acc[HID];
#pragma unroll
    for (int n = 0; n < HID; n++) acc[n] = 0.f;

    const float4* xr = reinterpret_cast<const float4*>(X + (size_t)node * K);
    const float4* xr2 = (MODE == 1) ? reinterpret_cast<const float4*>(X2 + (size_t)node * K) : nullptr;
#pragma unroll 1
    for (int k4 = 0; k4 < K / 4; k4++) {
        float4 v = __ldg(xr + k4);
        if (MODE == 1) {
            float4 w = __ldg(xr2 + k4);
            v.x += w.x; v.y += w.y; v.z += w.z; v.w += w.w;
        }
        float xv[4] = {v.x, v.y, v.z, v.w};
#pragma unroll
        for (int kk = 0; kk < 4; kk++) {
            const float* wr = &Ws[(k4 * 4 + kk) * HID];
#pragma unroll
            for (int n = 0; n < HID; n++) acc[n] = fmaf(xv[kk], wr[n], acc[n]);
        }
    }

    if (MODE == 0) {
        float s = 0.f, d = 0.f;
#pragma unroll
        for (int n = 0; n < HID; n++) { s += acc[n] * sv1[n]; d += acc[n] * sv2[n]; }
        S[node] = s;
        D[node] = d;
    } else {
#pragma unroll
        for (int n = 0; n < HID; n++) acc[n] = fmaxf(acc[n] + sv1[n], 0.f);
    }
    float4* hr = reinterpret_cast<float4*>(H + (size_t)node * HID);
#pragma unroll
    for (int i = 0; i < HID / 4; i++)
        hr[i] = make_float4(acc[4 * i], acc[4 * i + 1], acc[4 * i + 2], acc[4 * i + 3]);
}

// ---------------- fused edge pass: logit + exp (no max; logits provably tiny) + agg -----
__global__ __launch_bounds__(256) void k_edge_agg(const int* __restrict__ EI,
                                                  const float* __restrict__ EA, int which) {
    int gid = blockIdx.x * blockDim.x + threadIdx.x;
    int e = gid >> 4;
    int q = gid & 15;
    if (e >= NEDGES) return;
    int lane = threadIdx.x & 31;
    int src = __ldg(EI + e);
    int dst = __ldg(EI + NEDGES + e);
    float ex = 0.f;
    if ((lane & 15) == 0) {
        float w0 = g_we[which * 2], w1 = g_we[which * 2 + 1];
        float lg = g_s[src] + g_d[dst] + __ldg(EA + 2 * e) * w0 + __ldg(EA + 2 * e + 1) * w1;
        lg = (lg > 0.f) ? lg : 0.2f * lg;  // leaky_relu 0.2
        ex = expf(lg);
        atomicAdd(&g_den[dst], ex);
    }
    ex = __shfl_sync(0xffffffffu, ex, lane & 16);
    float4 h4 = *reinterpret_cast<const float4*>(&g_h[(size_t)src * 64 + q * 4]);
    float vx = ex * h4.x, vy = ex * h4.y, vz = ex * h4.z, vw = ex * h4.w;
    asm volatile("red.global.add.v4.f32 [%0], {%1,%2,%3,%4};"
                 :: "l"(&g_agg[(size_t)dst * 64 + q * 4]),
                    "f"(vx), "f"(vy), "f"(vz), "f"(vw)
                 : "memory");
}

// ---------------- normalize + bias + relu (float4), re-zero agg after read -----------
__global__ void k_node_fin(const float* __restrict__ bias, float* __restrict__ Y) {
    int gid = blockIdx.x * blockDim.x + threadIdx.x;  // one per 4 channels
    if (gid >= NNODES * 16) return;
    int node = gid >> 4;
    int q = gid & 15;
    float rd = 1.f / fmaxf(g_den[node], 1e-16f);
    float4* ap = reinterpret_cast<float4*>(&g_agg[(size_t)node * 64 + q * 4]);
    float4 a = *ap;
    *ap = make_float4(0.f, 0.f, 0.f, 0.f);  // same-thread read->write: race-free
    const float4 b = *reinterpret_cast<const float4*>(bias + q * 4);
    float4 y;
    y.x = fmaxf(a.x * rd + b.x, 0.f);
    y.y = fmaxf(a.y * rd + b.y, 0.f);
    y.z = fmaxf(a.z * rd + b.z, 0.f);
    y.w = fmaxf(a.w * rd + b.w, 0.f);
    *reinterpret_cast<float4*>(Y + (size_t)node * 64 + q * 4) = y;
}

// ================= fully fused edge MLP (gather + 5 pure-fp16 HMMA layers) =========
// R15 structure; kt loop unroll-2; float4 final output copy.
// SMEM map (dynamic, 77696 B):
//   [0, 34816)       A hi  (128 rows x 272 B stride)
//   [0, 74240)       final fp32 staging (reuses A after last mainloop)
//   [74240, 77696)   consts: We0(128f) be0(64f) b0..b3(4x128f) b4(160f)
__device__ __forceinline__ void store_hi2(char* p, float x, float y) {
    __half2 h = __floats2half2_rn(x, y);
    *reinterpret_cast<uint32_t*>(p) = *reinterpret_cast<uint32_t*>(&h);
}

template <int NTW>
__device__ __forceinline__ void mlp_mainloop(
    const char* sm, const uint32_t* __restrict__ Bf,
    int wm, int wn, int lane, float (&acc)[4][NTW][4]) {
    constexpr int NT = 4 * NTW;
    const int g = lane >> 2, t = lane & 3;
#pragma unroll
    for (int a = 0; a < 4; a++)
#pragma unroll
        for (int b = 0; b < NTW; b++)
#pragma unroll
            for (int c = 0; c < 4; c++) acc[a][b][c] = 0.f;
#pragma unroll 2
    for (int kt = 0; kt < 8; kt++) {
        uint32_t bh[NTW][2];
        const uint32_t* bp = Bf + ((size_t)(kt * NT + wn * NTW) * 32 + lane) * 2;
#pragma unroll
        for (int nt = 0; nt < NTW; nt++) {
            bh[nt][0] = __ldg(bp + nt * 64 + 0);
            bh[nt][1] = __ldg(bp + nt * 64 + 1);
        }
#pragma unroll
        for (int mt = 0; mt < 4; mt++) {
            const char* Ah = sm + (wm * 64 + mt * 16 + g) * 272 + (kt * 16 + t * 2) * 2;
            uint32_t ah[4];
            ah[0] = *reinterpret_cast<const uint32_t*>(Ah);
            ah[1] = *reinterpret_cast<const uint32_t*>(Ah + 8 * 272);
            ah[2] = *reinterpret_cast<const uint32_t*>(Ah + 16);
            ah[3] = *reinterpret_cast<const uint32_t*>(Ah + 8 * 272 + 16);
#pragma unroll
            for (int nt = 0; nt < NTW; nt++) {
                mma_f16(acc[mt][nt], ah, bh[nt]);
            }
        }
    }
}

__global__ __launch_bounds__(256) void k_mlp(
    const int* __restrict__ EI, const float* __restrict__ EA,
    const float* __restrict__ Y4, const uint32_t* __restrict__ Bf,
    const float* __restrict__ We0, const float* __restrict__ be0,
    const float* __restrict__ b3, const float* __restrict__ bm0,
    const float* __restrict__ bm1, const float* __restrict__ bm2,
    const float* __restrict__ b4, float* __restrict__ out) {
    extern __shared__ char sm[];
    float* cs = reinterpret_cast<float*>(sm + 74240);
    const int tid = threadIdx.x;
    const int wid = tid >> 5, lane = tid & 31;
    const int g = lane >> 2, t = lane & 3;
    const int wm = wid >> 2, wn = wid & 3;
    const int m0 = blockIdx.x * 128;

    // consts -> smem
    for (int i = tid; i < 128; i += 256) {
        cs[i] = __ldg(We0 + i);
        cs[192 + i] = __ldg(b3 + i);
        cs[320 + i] = __ldg(bm0 + i);
        cs[448 + i] = __ldg(bm1 + i);
        cs[576 + i] = __ldg(bm2 + i);
    }
    for (int i = tid; i < 64; i += 256) cs[128 + i] = __ldg(be0 + i);
    for (int i = tid; i < 160; i += 256) cs[704 + i] = (i < 145) ? __ldg(b4 + i) : 0.f;
    __syncthreads();

    // stage layer-0 input: [y4[src]+y4[dst] | relu(ea@We0+be0)] -> fp16 SMEM
#pragma unroll
    for (int it = 0; it < 16; it++) {
        int i = tid + it * 256;
        int row = i >> 5, col = (i & 31) * 4;
        int e = m0 + row;
        float4 v;
        if (col < 64) {
            int s = __ldg(EI + e), d = __ldg(EI + NEDGES + e);
            float4 a = *reinterpret_cast<const float4*>(Y4 + (size_t)s * 64 + col);
            float4 b = *reinterpret_cast<const float4*>(Y4 + (size_t)d * 64 + col);
            v = make_float4(a.x + b.x, a.y + b.y, a.z + b.z, a.w + b.w);
        } else {
            int c2 = col - 64;
            float e0 = __ldg(EA + 2 * e), e1 = __ldg(EA + 2 * e + 1);
            v.x = fmaxf(e0 * cs[c2 + 0] + e1 * cs[64 + c2 + 0] + cs[128 + c2 + 0], 0.f);
            v.y = fmaxf(e0 * cs[c2 + 1] + e1 * cs[64 + c2 + 1] + cs[128 + c2 + 1], 0.f);
            v.z = fmaxf(e0 * cs[c2 + 2] + e1 * cs[64 + c2 + 2] + cs[128 + c2 + 2], 0.f);
            v.w = fmaxf(e0 * cs[c2 + 3] + e1 * cs[64 + c2 + 3] + cs[128 + c2 + 3], 0.f);
        }
        char* p = sm + row * 272 + col * 2;
        store_hi2(p, v.x, v.y);
        store_hi2(p + 4, v.z, v.w);
    }
    __syncthreads();

    // 4 hidden layers, resident in SMEM
#pragma unroll 1
    for (int l = 0; l < 4; l++) {
        float acc[4][4][4];
        mlp_mainloop<4>(sm, Bf + l * 8192, wm, wn, lane, acc);
        __syncthreads();  // all A reads done before overwrite
        const float* bs = cs + 192 + l * 128;
#pragma unroll
        for (int mt = 0; mt < 4; mt++) {
            int r0 = wm * 64 + mt * 16 + g;
#pragma unroll
            for (int nt = 0; nt < 4; nt++) {
                int c0 = wn * 32 + nt * 8 + t * 2;
                float bv0 = bs[c0], bv1 = bs[c0 + 1];
                char* p0 = sm + r0 * 272 + c0 * 2;
                store_hi2(p0, fmaxf(acc[mt][nt][0] + bv0, 0.f),
                              fmaxf(acc[mt][nt][1] + bv1, 0.f));
                store_hi2(p0 + 8 * 272, fmaxf(acc[mt][nt][2] + bv0, 0.f),
                                        fmaxf(acc[mt][nt][3] + bv1, 0.f));
            }
        }
        __syncthreads();
    }

    // final layer: 160 padded cols, 145 real
    {
        float acc[4][5][4];
        mlp_mainloop<5>(sm, Bf + 4 * 8192, wm, wn, lane, acc);
        __syncthreads();
        float* epi = reinterpret_cast<float*>(sm);
        const float* bs = cs + 704;
#pragma unroll
        for (int mt = 0; mt < 4; mt++) {
            int r0 = wm * 64 + mt * 16 + g;
#pragma unroll
            for (int nt = 0; nt < 5; nt++) {
                int c0 = wn * 40 + nt * 8 + t * 2;
                float bv0 = bs[c0], bv1 = bs[c0 + 1];
                if (c0 < 145) {
                    epi[r0 * 145 + c0] = acc[mt][nt][0] + bv0;
                    epi[(r0 + 8) * 145 + c0] = acc[mt][nt][2] + bv0;
                }
                if (c0 + 1 < 145) {
                    epi[r0 * 145 + c0 + 1] = acc[mt][nt][1] + bv1;
                    epi[(r0 + 8) * 145 + c0 + 1] = acc[mt][nt][3] + bv1;
                }
            }
        }
        __syncthreads();
        // 128*145*4B = 74240 B = 4640 float4; tile base is 16B-aligned for every CTA
        const float4* ep4 = reinterpret_cast<const float4*>(epi);
        float4* Co4 = reinterpret_cast<float4*>(out + (size_t)m0 * 145);
#pragma unroll 4
        for (int i = tid; i < 4640; i += 256) Co4[i] = ep4[i];
    }
}

// ---------------- launch ----------------
extern "C" void kernel_launch(void* const* d_in, const int* in_sizes, int n_in,
                              void* d_out, int out_size) {
    const float* x   = (const float*)d_in[0];
    const int*   ei  = (const int*)d_in[1];
    const float* ea  = (const float*)d_in[2];
    const float* Wg1 = (const float*)d_in[4];
    const float* as1 = (const float*)d_in[5];
    const float* ad1 = (const float*)d_in[6];
    const float* We1 = (const float*)d_in[7];
    const float* ae1 = (const float*)d_in[8];
    const float* bg1 = (const float*)d_in[9];
    const float* Wg2 = (const float*)d_in[10];
    const float* as2 = (const float*)d_in[11];
    const float* ad2 = (const float*)d_in[12];
    const float* We2 = (const float*)d_in[13];
    const float* ae2 = (const float*)d_in[14];
    const float* bg2 = (const float*)d_in[15];
    const float* W2  = (const float*)d_in[16];
    const float* b2  = (const float*)d_in[17];
    const float* We0 = (const float*)d_in[18];
    const float* be0 = (const float*)d_in[19];
    const float* W3  = (const float*)d_in[20];
    const float* b3  = (const float*)d_in[21];
    const float* Wm0 = (const float*)d_in[22];
    const float* bm0 = (const float*)d_in[23];
    const float* Wm1 = (const float*)d_in[24];
    const float* bm1 = (const float*)d_in[25];
    const float* Wm2 = (const float*)d_in[26];
    const float* bm2 = (const float*)d_in[27];
    const float* W4  = (const float*)d_in[28];
    const float* b4  = (const float*)d_in[29];
    float* out = (float*)d_out;

    float *p_h, *p_s, *p_d, *p_y0, *p_y1, *p_y4;
    uint32_t* p_BF;
    cudaGetSymbolAddress((void**)&p_h, g_h);
    cudaGetSymbolAddress((void**)&p_s, g_s);
    cudaGetSymbolAddress((void**)&p_d, g_d);
    cudaGetSymbolAddress((void**)&p_y0, g_y0);
    cudaGetSymbolAddress((void**)&p_y1, g_y1);
    cudaGetSymbolAddress((void**)&p_y4, g_y4);
    cudaGetSymbolAddress((void**)&p_BF, g_Bfrag);

    const int SMM = 77696;  // dynamic smem for k_mlp
    cudaFuncSetAttribute(k_mlp, cudaFuncAttributeMaxDynamicSharedMemorySize, SMM);

    const int nodeGrid = (NNODES + 127) / 128;
    const int finGrid  = (NNODES * 16 + 255) / 256;
    const int aggGrid  = (NEDGES * 16) / 256;  // 50000

    k_prep_we<<<1, 32>>>(We1, ae1, We2, ae2);

    // B fragments for the 5 tensor GEMMs (fp16 hi only)
    k_prep_bfrag<<<(8 * 16 * 32 + 255) / 256, 256>>>(W3,  128, 16, p_BF + 0 * 8192);
    k_prep_bfrag<<<(8 * 16 * 32 + 255) / 256, 256>>>(Wm0, 128, 16, p_BF + 1 * 8192);
    k_prep_bfrag<<<(8 * 16 * 32 + 255) / 256, 256>>>(Wm1, 128, 16, p_BF + 2 * 8192);
    k_prep_bfrag<<<(8 * 16 * 32 + 255) / 256, 256>>>(Wm2, 128, 16, p_BF + 3 * 8192);
    k_prep_bfrag<<<(8 * 20 * 32 + 255) / 256, 256>>>(W4,  145, 20, p_BF + 4 * 8192);

    // ---- GAT layer 1 (agg/den zero at entry; every pass restores what it consumed) ----
    k_node_gemm<128, 0, false><<<nodeGrid, 128>>>(x, nullptr, Wg1, as1, ad1, p_h, p_s, p_d);
    k_edge_agg<<<aggGrid, 256>>>(ei, ea, 0);
    k_node_fin<<<finGrid, 256>>>(bg1, p_y0);  // reads agg/den, re-zeros agg

    // ---- GAT layer 2 (gemm zeroes den before agg#2 accumulates) ----
    k_node_gemm<64, 0, true><<<nodeGrid, 128>>>(p_y0, nullptr, Wg2, as2, ad2, p_h, p_s, p_d);
    k_edge_agg<<<aggGrid, 256>>>(ei, ea, 1);
    k_node_fin<<<finGrid, 256>>>(bg2, p_y1);  // reads agg/den, re-zeros agg

    // ---- l2: y4 = relu((y0+y1) @ W2 + b2); zeroes den for next replay ----
    k_node_gemm<64, 1, true><<<nodeGrid, 128>>>(p_y0, p_y1, W2, b2, nullptr, p_y4, nullptr, nullptr);

    // ---- fully fused edge MLP (pure fp16, 1 mma/tile) ----
    k_mlp<<<NEDGES / 128, 256, SMM>>>(ei, ea, p_y4, p_BF, We0, be0, b3, bm0, bm1, bm2, b4, out);
}

// round 17
// speedup vs baseline: 1.4792x; 1.0668x over previous
#include <cuda_runtime.h>
#include <cuda_fp16.h>
#include <cstdint>

#define NNODES 50000
#define NEDGES 800000
#define HID 64

// ---------------- scratch (static device globals; zero-initialized at load) ----------
// g_agg re-zeroed by k_node_fin after consumption; g_den re-zeroed by the node GEMM
// that follows each fin (and by l2 gemm for next replay) -> state restored every call.
__device__ float    g_h[NNODES * HID];
__device__ float    g_s[NNODES];
__device__ float    g_d[NNODES];
__device__ float    g_den[NNODES];
__device__ float    g_agg[NNODES * HID];
__device__ float    g_y0[NNODES * HID];
__device__ float    g_y1[NNODES * HID];
__device__ float    g_y4[NNODES * HID];
__device__ float    g_we[4];
// B fragments (fp16 hi only), mma register order:
// layers 0-3 (NT=16): 8192 u32 each; layer 4 (NT=20): 10240 u32
__device__ uint32_t g_Bfrag[4 * 8192 + 10240];

__device__ __forceinline__ void mma_f16(float* c, const uint32_t* a, const uint32_t* b) {
    asm volatile(
        "mma.sync.aligned.m16n8k16.row.col.f32.f16.f16.f32 "
        "{%0,%1,%2,%3}, {%4,%5,%6,%7}, {%8,%9}, {%0,%1,%2,%3};"
        : "+f"(c[0]), "+f"(c[1]), "+f"(c[2]), "+f"(c[3])
        : "r"(a[0]), "r"(a[1]), "r"(a[2]), "r"(a[3]), "r"(b[0]), "r"(b[1]));
}

// ---------------- merged prep: all 5 B-fragment layers + g_we, one launch ------------
__global__ void k_prep_all(const float* __restrict__ W3, const float* __restrict__ Wm0,
                           const float* __restrict__ Wm1, const float* __restrict__ Wm2,
                           const float* __restrict__ W4, uint32_t* __restrict__ outb,
                           const float* __restrict__ We1, const float* __restrict__ ae1,
                           const float* __restrict__ We2, const float* __restrict__ ae2) {
    int layer = blockIdx.y;
    if (layer == 5) {
        int t = threadIdx.x;
        if (blockIdx.x == 0 && t < 4) {
            const float* W = (t < 2) ? We1 : We2;
            const float* a = (t < 2) ? ae1 : ae2;
            int r = t & 1;
            float s = 0.f;
            for (int j = 0; j < HID; j++) s += W[r * HID + j] * a[j];
            g_we[t] = s;
        }
        return;
    }
    const float* W = (layer == 0) ? W3 : (layer == 1) ? Wm0 : (layer == 2) ? Wm1
                   : (layer == 3) ? Wm2 : W4;
    const int Nreal = (layer == 4) ? 145 : 128;
    const int NT = (layer == 4) ? 20 : 16;
    uint32_t* out = outb + layer * 8192;

    int idx = blockIdx.x * blockDim.x + threadIdx.x;
    if (idx >= 8 * NT * 32) return;
    int lane = idx & 31;
    int nt = (idx >> 5) % NT;
    int kt = idx / (NT * 32);
    int g = lane >> 2, t = lane & 3;
    int n = nt * 8 + g;
    int k0 = kt * 16 + t * 2;
    float w0 = (n < Nreal) ? __ldg(W + (k0 + 0) * Nreal + n) : 0.f;
    float w1 = (n < Nreal) ? __ldg(W + (k0 + 1) * Nreal + n) : 0.f;
    float w2 = (n < Nreal) ? __ldg(W + (k0 + 8) * Nreal + n) : 0.f;
    float w3 = (n < Nreal) ? __ldg(W + (k0 + 9) * Nreal + n) : 0.f;
    __half2 h0 = __floats2half2_rn(w0, w1);
    __half2 h1 = __floats2half2_rn(w2, w3);
    uint32_t* o = out + (size_t)idx * 2;
    o[0] = *reinterpret_cast<uint32_t*>(&h0);
    o[1] = *reinterpret_cast<uint32_t*>(&h1);
}

// ---------------- node GEMM (fp32 scalar); ZD: zero g_den[node] for next pass -------
template <int K, int MODE, bool ZD>
__global__ __launch_bounds__(128) void k_node_gemm(
    const float* __restrict__ X, const float* __restrict__ X2,
    const float* __restrict__ W, const float* __restrict__ v1,
    const float* __restrict__ v2,
    float* __restrict__ H, float* __restrict__ S, float* __restrict__ D) {
    __shared__ float Ws[K * HID];
    __shared__ float sv1[HID], sv2[HID];
    int tid = threadIdx.x;
    for (int i = tid; i < K * HID; i += 128) Ws[i] = W[i];
    if (tid < HID) {
        sv1[tid] = v1 ? v1[tid] : 0.f;
        sv2[tid] = v2 ? v2[tid] : 0.f;
    }
    __syncthreads();
    int node = blockIdx.x * 128 + tid;
    if (node >= NNODES) return;

    if (ZD) g_den[node] = 0.f;  // reset for the next edge-agg pass / next replay

    float acc[HID];
#pragma unroll
    for (int n = 0; n < HID; n++) acc[n] = 0.f;

    const float4* xr = reinterpret_cast<const float4*>(X + (size_t)node * K);
    const float4* xr2 = (MODE == 1) ? reinterpret_cast<const float4*>(X2 + (size_t)node * K) : nullptr;
#pragma unroll 1
    for (int k4 = 0; k4 < K / 4; k4++) {
        float4 v = __ldg(xr + k4);
        if (MODE == 1) {
            float4 w = __ldg(xr2 + k4);
            v.x += w.x; v.y += w.y; v.z += w.z; v.w += w.w;
        }
        float xv[4] = {v.x, v.y, v.z, v.w};
#pragma unroll
        for (int kk = 0; kk < 4; kk++) {
            const float* wr = &Ws[(k4 * 4 + kk) * HID];
#pragma unroll
            for (int n = 0; n < HID; n++) acc[n] = fmaf(xv[kk], wr[n], acc[n]);
        }
    }

    if (MODE == 0) {
        float s = 0.f, d = 0.f;
#pragma unroll
        for (int n = 0; n < HID; n++) { s += acc[n] * sv1[n]; d += acc[n] * sv2[n]; }
        S[node] = s;
        D[node] = d;
    } else {
#pragma unroll
        for (int n = 0; n < HID; n++) acc[n] = fmaxf(acc[n] + sv1[n], 0.f);
    }
    float4* hr = reinterpret_cast<float4*>(H + (size_t)node * HID);
#pragma unroll
    for (int i = 0; i < HID / 4; i++)
        hr[i] = make_float4(acc[4 * i], acc[4 * i + 1], acc[4 * i + 2], acc[4 * i + 3]);
}

// ---------------- fused edge pass: logit + exp (no max; logits provably tiny) + agg -----
__global__ __launch_bounds__(256) void k_edge_agg(const int* __restrict__ EI,
                                                  const float* __restrict__ EA, int which) {
    int gid = blockIdx.x * blockDim.x + threadIdx.x;
    int e = gid >> 4;
    int q = gid & 15;
    if (e >= NEDGES) return;
    int lane = threadIdx.x & 31;
    int src = __ldg(EI + e);
    int dst = __ldg(EI + NEDGES + e);
    float ex = 0.f;
    if ((lane & 15) == 0) {
        float w0 = g_we[which * 2], w1 = g_we[which * 2 + 1];
        float lg = g_s[src] + g_d[dst] + __ldg(EA + 2 * e) * w0 + __ldg(EA + 2 * e + 1) * w1;
        lg = (lg > 0.f) ? lg : 0.2f * lg;  // leaky_relu 0.2
        ex = expf(lg);
        atomicAdd(&g_den[dst], ex);
    }
    ex = __shfl_sync(0xffffffffu, ex, lane & 16);
    float4 h4 = *reinterpret_cast<const float4*>(&g_h[(size_t)src * 64 + q * 4]);
    float vx = ex * h4.x, vy = ex * h4.y, vz = ex * h4.z, vw = ex * h4.w;
    asm volatile("red.global.add.v4.f32 [%0], {%1,%2,%3,%4};"
                 :: "l"(&g_agg[(size_t)dst * 64 + q * 4]),
                    "f"(vx), "f"(vy), "f"(vz), "f"(vw)
                 : "memory");
}

// ---------------- normalize + bias + relu (float4), re-zero agg after read -----------
__global__ void k_node_fin(const float* __restrict__ bias, float* __restrict__ Y) {
    int gid = blockIdx.x * blockDim.x + threadIdx.x;  // one per 4 channels
    if (gid >= NNODES * 16) return;
    int node = gid >> 4;
    int q = gid & 15;
    float rd = 1.f / fmaxf(g_den[node], 1e-16f);
    float4* ap = reinterpret_cast<float4*>(&g_agg[(size_t)node * 64 + q * 4]);
    float4 a = *ap;
    *ap = make_float4(0.f, 0.f, 0.f, 0.f);  // same-thread read->write: race-free
    const float4 b = *reinterpret_cast<const float4*>(bias + q * 4);
    float4 y;
    y.x = fmaxf(a.x * rd + b.x, 0.f);
    y.y = fmaxf(a.y * rd + b.y, 0.f);
    y.z = fmaxf(a.z * rd + b.z, 0.f);
    y.w = fmaxf(a.w * rd + b.w, 0.f);
    *reinterpret_cast<float4*>(Y + (size_t)node * 64 + q * 4) = y;
}

// ================= fully fused edge MLP (gather + 5 pure-fp16 HMMA layers) =========
// R16 structure + ping-pong A buffers (1 sync/layer) + uint2 B-fragment loads.
// SMEM map (dynamic, 77696 B):
//   [0, 34816)       buf0 (128 rows x 272 B stride, fp16)
//   [34816, 69632)   buf1
//   [0, 74240)       final fp32 staging (reuses both bufs after last mainloop)
//   [74240, 77696)   consts: We0(128f) be0(64f) b0..b3(4x128f) b4(160f)
__device__ __forceinline__ void store_hi2(char* p, float x, float y) {
    __half2 h = __floats2half2_rn(x, y);
    *reinterpret_cast<uint32_t*>(p) = *reinterpret_cast<uint32_t*>(&h);
}

template <int NTW>
__device__ __forceinline__ void mlp_mainloop(
    const char* sm, const uint32_t* __restrict__ Bf,
    int wm, int wn, int lane, float (&acc)[4][NTW][4]) {
    constexpr int NT = 4 * NTW;
    const int g = lane >> 2, t = lane & 3;
#pragma unroll
    for (int a = 0; a < 4; a++)
#pragma unroll
        for (int b = 0; b < NTW; b++)
#pragma unroll
            for (int c = 0; c < 4; c++) acc[a][b][c] = 0.f;
#pragma unroll 2
    for (int kt = 0; kt < 8; kt++) {
        uint32_t bh[NTW][2];
        const uint32_t* bp = Bf + ((size_t)(kt * NT + wn * NTW) * 32 + lane) * 2;
#pragma unroll
        for (int nt = 0; nt < NTW; nt++) {
            uint2 bv = __ldg(reinterpret_cast<const uint2*>(bp + nt * 64));
            bh[nt][0] = bv.x;
            bh[nt][1] = bv.y;
        }
#pragma unroll
        for (int mt = 0; mt < 4; mt++) {
            const char* Ah = sm + (wm * 64 + mt * 16 + g) * 272 + (kt * 16 + t * 2) * 2;
            uint32_t ah[4];
            ah[0] = *reinterpret_cast<const uint32_t*>(Ah);
            ah[1] = *reinterpret_cast<const uint32_t*>(Ah + 8 * 272);
            ah[2] = *reinterpret_cast<const uint32_t*>(Ah + 16);
            ah[3] = *reinterpret_cast<const uint32_t*>(Ah + 8 * 272 + 16);
#pragma unroll
            for (int nt = 0; nt < NTW; nt++) {
                mma_f16(acc[mt][nt], ah, bh[nt]);
            }
        }
    }
}

__global__ __launch_bounds__(256) void k_mlp(
    const int* __restrict__ EI, const float* __restrict__ EA,
    const float* __restrict__ Y4, const uint32_t* __restrict__ Bf,
    const float* __restrict__ We0, const float* __restrict__ be0,
    const float* __restrict__ b3, const float* __restrict__ bm0,
    const float* __restrict__ bm1, const float* __restrict__ bm2,
    const float* __restrict__ b4, float* __restrict__ out) {
    extern __shared__ char sm[];
    float* cs = reinterpret_cast<float*>(sm + 74240);
    const int tid = threadIdx.x;
    const int wid = tid >> 5, lane = tid & 31;
    const int g = lane >> 2, t = lane & 3;
    const int wm = wid >> 2, wn = wid & 3;
    const int m0 = blockIdx.x * 128;

    // consts -> smem
    for (int i = tid; i < 128; i += 256) {
        cs[i] = __ldg(We0 + i);
        cs[192 + i] = __ldg(b3 + i);
        cs[320 + i] = __ldg(bm0 + i);
        cs[448 + i] = __ldg(bm1 + i);
        cs[576 + i] = __ldg(bm2 + i);
    }
    for (int i = tid; i < 64; i += 256) cs[128 + i] = __ldg(be0 + i);
    for (int i = tid; i < 160; i += 256) cs[704 + i] = (i < 145) ? __ldg(b4 + i) : 0.f;
    __syncthreads();

    // stage layer-0 input into buf0: [y4[src]+y4[dst] | relu(ea@We0+be0)] -> fp16
#pragma unroll
    for (int it = 0; it < 16; it++) {
        int i = tid + it * 256;
        int row = i >> 5, col = (i & 31) * 4;
        int e = m0 + row;
        float4 v;
        if (col < 64) {
            int s = __ldg(EI + e), d = __ldg(EI + NEDGES + e);
            float4 a = *reinterpret_cast<const float4*>(Y4 + (size_t)s * 64 + col);
            float4 b = *reinterpret_cast<const float4*>(Y4 + (size_t)d * 64 + col);
            v = make_float4(a.x + b.x, a.y + b.y, a.z + b.z, a.w + b.w);
        } else {
            int c2 = col - 64;
            float e0 = __ldg(EA + 2 * e), e1 = __ldg(EA + 2 * e + 1);
            v.x = fmaxf(e0 * cs[c2 + 0] + e1 * cs[64 + c2 + 0] + cs[128 + c2 + 0], 0.f);
            v.y = fmaxf(e0 * cs[c2 + 1] + e1 * cs[64 + c2 + 1] + cs[128 + c2 + 1], 0.f);
            v.z = fmaxf(e0 * cs[c2 + 2] + e1 * cs[64 + c2 + 2] + cs[128 + c2 + 2], 0.f);
            v.w = fmaxf(e0 * cs[c2 + 3] + e1 * cs[64 + c2 + 3] + cs[128 + c2 + 3], 0.f);
        }
        char* p = sm + row * 272 + col * 2;
        store_hi2(p, v.x, v.y);
        store_hi2(p + 4, v.z, v.w);
    }
    __syncthreads();

    // 4 hidden layers, ping-pong buffers: one sync per layer
    int cur = 0;
#pragma unroll 1
    for (int l = 0; l < 4; l++) {
        float acc[4][4][4];
        mlp_mainloop<4>(sm + cur, Bf + l * 8192, wm, wn, lane, acc);
        const int nxt = 34816 - cur;  // other buffer: disjoint, no pre-sync needed
        const float* bs = cs + 192 + l * 128;
#pragma unroll
        for (int mt = 0; mt < 4; mt++) {
            int r0 = wm * 64 + mt * 16 + g;
#pragma unroll
            for (int nt = 0; nt < 4; nt++) {
                int c0 = wn * 32 + nt * 8 + t * 2;
                float bv0 = bs[c0], bv1 = bs[c0 + 1];
                char* p0 = sm + nxt + r0 * 272 + c0 * 2;
                store_hi2(p0, fmaxf(acc[mt][nt][0] + bv0, 0.f),
                              fmaxf(acc[mt][nt][1] + bv1, 0.f));
                store_hi2(p0 + 8 * 272, fmaxf(acc[mt][nt][2] + bv0, 0.f),
                                        fmaxf(acc[mt][nt][3] + bv1, 0.f));
            }
        }
        __syncthreads();
        cur = nxt;
    }

    // final layer: 160 padded cols, 145 real (reads cur == buf0)
    {
        float acc[4][5][4];
        mlp_mainloop<5>(sm + cur, Bf + 4 * 8192, wm, wn, lane, acc);
        __syncthreads();  // fp32 staging overwrites both buffers
        float* epi = reinterpret_cast<float*>(sm);
        const float* bs = cs + 704;
#pragma unroll
        for (int mt = 0; mt < 4; mt++) {
            int r0 = wm * 64 + mt * 16 + g;
#pragma unroll
            for (int nt = 0; nt < 5; nt++) {
                int c0 = wn * 40 + nt * 8 + t * 2;
                float bv0 = bs[c0], bv1 = bs[c0 + 1];
                if (c0 < 145) {
                    epi[r0 * 145 + c0] = acc[mt][nt][0] + bv0;
                    epi[(r0 + 8) * 145 + c0] = acc[mt][nt][2] + bv0;
                }
                if (c0 + 1 < 145) {
                    epi[r0 * 145 + c0 + 1] = acc[mt][nt][1] + bv1;
                    epi[(r0 + 8) * 145 + c0 + 1] = acc[mt][nt][3] + bv1;
                }
            }
        }
        __syncthreads();
        // 128*145*4B = 74240 B = 4640 float4; tile base is 16B-aligned for every CTA
        const float4* ep4 = reinterpret_cast<const float4*>(epi);
        float4* Co4 = reinterpret_cast<float4*>(out + (size_t)m0 * 145);
#pragma unroll 4
        for (int i = tid; i < 4640; i += 256) Co4[i] = ep4[i];
    }
}

// ---------------- launch ----------------
extern "C" void kernel_launch(void* const* d_in, const int* in_sizes, int n_in,
                              void* d_out, int out_size) {
    const float* x   = (const float*)d_in[0];
    const int*   ei  = (const int*)d_in[1];
    const float* ea  = (const float*)d_in[2];
    const float* Wg1 = (const float*)d_in[4];
    const float* as1 = (const float*)d_in[5];
    const float* ad1 = (const float*)d_in[6];
    const float* We1 = (const float*)d_in[7];
    const float* ae1 = (const float*)d_in[8];
    const float* bg1 = (const float*)d_in[9];
    const float* Wg2 = (const float*)d_in[10];
    const float* as2 = (const float*)d_in[11];
    const float* ad2 = (const float*)d_in[12];
    const float* We2 = (const float*)d_in[13];
    const float* ae2 = (const float*)d_in[14];
    const float* bg2 = (const float*)d_in[15];
    const float* W2  = (const float*)d_in[16];
    const float* b2  = (const float*)d_in[17];
    const float* We0 = (const float*)d_in[18];
    const float* be0 = (const float*)d_in[19];
    const float* W3  = (const float*)d_in[20];
    const float* b3  = (const float*)d_in[21];
    const float* Wm0 = (const float*)d_in[22];
    const float* bm0 = (const float*)d_in[23];
    const float* Wm1 = (const float*)d_in[24];
    const float* bm1 = (const float*)d_in[25];
    const float* Wm2 = (const float*)d_in[26];
    const float* bm2 = (const float*)d_in[27];
    const float* W4  = (const float*)d_in[28];
    const float* b4  = (const float*)d_in[29];
    float* out = (float*)d_out;

    float *p_h, *p_s, *p_d, *p_y0, *p_y1, *p_y4;
    uint32_t* p_BF;
    cudaGetSymbolAddress((void**)&p_h, g_h);
    cudaGetSymbolAddress((void**)&p_s, g_s);
    cudaGetSymbolAddress((void**)&p_d, g_d);
    cudaGetSymbolAddress((void**)&p_y0, g_y0);
    cudaGetSymbolAddress((void**)&p_y1, g_y1);
    cudaGetSymbolAddress((void**)&p_y4, g_y4);
    cudaGetSymbolAddress((void**)&p_BF, g_Bfrag);

    const int SMM = 77696;  // dynamic smem for k_mlp
    cudaFuncSetAttribute(k_mlp, cudaFuncAttributeMaxDynamicSharedMemorySize, SMM);

    const int nodeGrid = (NNODES + 127) / 128;
    const int finGrid  = (NNODES * 16 + 255) / 256;
    const int aggGrid  = (NEDGES * 16) / 256;  // 50000

    // ---- single merged prep launch (5 B-fragment layers + g_we) ----
    k_prep_all<<<dim3(20, 6), 256>>>(W3, Wm0, Wm1, Wm2, W4, p_BF, We1, ae1, We2, ae2);

    // ---- GAT layer 1 (agg/den zero at entry; every pass restores what it consumed) ----
    k_node_gemm<128, 0, false><<<nodeGrid, 128>>>(x, nullptr, Wg1, as1, ad1, p_h, p_s, p_d);
    k_edge_agg<<<aggGrid, 256>>>(ei, ea, 0);
    k_node_fin<<<finGrid, 256>>>(bg1, p_y0);  // reads agg/den, re-zeros agg

    // ---- GAT layer 2 (gemm zeroes den before agg#2 accumulates) ----
    k_node_gemm<64, 0, true><<<nodeGrid, 128>>>(p_y0, nullptr, Wg2, as2, ad2, p_h, p_s, p_d);
    k_edge_agg<<<aggGrid, 256>>>(ei, ea, 1);
    k_node_fin<<<finGrid, 256>>>(bg2, p_y1);  // reads agg/den, re-zeros agg

    // ---- l2: y4 = relu((y0+y1) @ W2 + b2); zeroes den for next replay ----
    k_node_gemm<64, 1, true><<<nodeGrid, 128>>>(p_y0, p_y1, W2, b2, nullptr, p_y4, nullptr, nullptr);

    // ---- fully fused edge MLP (pure fp16, ping-pong buffers) ----
    k_mlp<<<NEDGES / 128, 256, SMM>>>(ei, ea, p_y4, p_BF, We0, be0, b3, bm0, bm1, bm2, b4, out);
}